// round 6
// baseline (speedup 1.0000x reference)
#include <cuda_runtime.h>
#include <cstdint>

// ---------------------------------------------------------------------------
// AdjGCN: 3-layer GCN forward, CSR-gather aggregation (no float atomics).
// CSR build runs on a forked side stream, overlapped with layer-1 GEMM.
// gemm128 inner loop uses packed fma.rn.f32x2 (2 MACs/instr, exact fp32).
// ---------------------------------------------------------------------------

#define MAXN 100000
#define MAXE 1600000
#define DH   128
#define DO   40

__device__ float g_bufA[(size_t)MAXN * DH];
__device__ float g_bufB[(size_t)MAXN * DH];
__device__ int   g_idx64;            // 1 if edge_index is int64, 0 if int32
__device__ int   g_rowptr[MAXN + 1];
__device__ int   g_deg[MAXN];
__device__ int   g_fill[MAXN];
__device__ int   g_esrc[MAXE];
__device__ float g_ews[MAXE];
__device__ int   g_partials[128];

// ---------------------------------------------------------------------------
__device__ __forceinline__ void load_edge(const void* ei, int nedges, int e,
                                          int& s, int& d) {
    if (g_idx64) {
        const long long* p = (const long long*)ei;
        s = (int)p[e];
        d = (int)p[(size_t)nedges + e];
    } else {
        const int* p = (const int*)ei;
        s = p[e];
        d = p[(size_t)nedges + e];
    }
}

// ------------------------------ CSR build ---------------------------------
__global__ void deg_zero_kernel(int* __restrict__ deg, int n,
                                const void* ei, int n_nodes) {
    int i = blockIdx.x * blockDim.x + threadIdx.x;
    if (i < n) deg[i] = 0;
    if (blockIdx.x == 0 && threadIdx.x == 0) {
        const long long* p = (const long long*)ei;
        int ok64 = 1;
        for (int k = 0; k < 32; k++) {
            long long v = p[k];
            if (v < 0 || v >= n_nodes) { ok64 = 0; break; }
        }
        g_idx64 = ok64;
    }
}

__global__ void deg_count_kernel(const void* __restrict__ ei, int ne,
                                 int* __restrict__ deg) {
    int e = blockIdx.x * blockDim.x + threadIdx.x;
    if (e < ne) {
        int s, d;
        load_edge(ei, ne, e, s, d);
        atomicAdd(&deg[d], 1);
    }
}

__global__ void scan_block_kernel(const int* __restrict__ deg,
                                  int* __restrict__ rowptr,
                                  int* __restrict__ partials, int n) {
    __shared__ int sm[1024];
    const int tid = threadIdx.x;
    int i = blockIdx.x * 1024 + tid;
    int v = (i < n) ? deg[i] : 0;
    sm[tid] = v;
    __syncthreads();
#pragma unroll
    for (int o = 1; o < 1024; o <<= 1) {
        int t = (tid >= o) ? sm[tid - o] : 0;
        __syncthreads();
        sm[tid] += t;
        __syncthreads();
    }
    if (i < n) rowptr[i] = sm[tid] - v;
    if (tid == 1023) partials[blockIdx.x] = sm[1023];
}

__global__ void scan_partials_kernel(int* __restrict__ partials, int nb) {
    __shared__ int sm[128];
    const int tid = threadIdx.x;
    int v = (tid < nb) ? partials[tid] : 0;
    sm[tid] = v;
    __syncthreads();
#pragma unroll
    for (int o = 1; o < 128; o <<= 1) {
        int t = (tid >= o) ? sm[tid - o] : 0;
        __syncthreads();
        sm[tid] += t;
        __syncthreads();
    }
    if (tid < nb) partials[tid] = sm[tid] - v;
}

__global__ void scan_add_kernel(int* __restrict__ rowptr,
                                const int* __restrict__ partials,
                                int* __restrict__ fill, int n, int ne) {
    int i = blockIdx.x * blockDim.x + threadIdx.x;
    if (i < n) {
        int v = rowptr[i] + partials[i >> 10];
        rowptr[i] = v;
        fill[i] = v;
    }
    if (i == 0) rowptr[n] = ne;
}

__global__ void csr_fill_kernel(const void* __restrict__ ei,
                                const float* __restrict__ ew, int ne,
                                int* __restrict__ fill,
                                int* __restrict__ esrc,
                                float* __restrict__ ews) {
    int e = blockIdx.x * blockDim.x + threadIdx.x;
    if (e < ne) {
        int s, d;
        load_edge(ei, ne, e, s, d);
        int pos = atomicAdd(&fill[d], 1);
        esrc[pos] = s;
        ews[pos] = ew[e];
    }
}

// ------------------------------ GEMMs -------------------------------------
// 128x128 W in smem (plain), X tile stored DUPLICATED as (x,x) float2 pairs.
// 64 rows/block, 256 threads; thread tile 8 rows x 4 cols; inner loop uses
// fma.rn.f32x2: x broadcast pair * W column pair -> 2 MACs per instruction.
__global__ void gemm128_kernel(const float* __restrict__ X,
                               const float* __restrict__ W,
                               float* __restrict__ Y, int nrows) {
    extern __shared__ float sm[];
    float* Ws = sm;                              // 128*128 floats [k][c]
    float2* Xs2 = (float2*)(sm + 128 * 128);     // 64 rows * 128 k, dup pairs
    const int tid = threadIdx.x;

    const float4* W4 = (const float4*)W;
    float4* Ws4 = (float4*)Ws;
#pragma unroll
    for (int i = tid; i < 128 * 32; i += 256) Ws4[i] = W4[i];

    const int row0 = blockIdx.x * 64;
    const float4* X4 = (const float4*)X;
#pragma unroll
    for (int i = tid; i < 64 * 32; i += 256) {
        int r = i >> 5, kq = i & 31;
        float4 v = (row0 + r < nrows) ? X4[(size_t)(row0 + r) * 32 + kq]
                                      : make_float4(0.f, 0.f, 0.f, 0.f);
        float2* dst = Xs2 + r * 128 + kq * 4;
        dst[0] = make_float2(v.x, v.x);
        dst[1] = make_float2(v.y, v.y);
        dst[2] = make_float2(v.z, v.z);
        dst[3] = make_float2(v.w, v.w);
    }
    __syncthreads();

    const int cg = tid & 31;    // cols 4*cg..4*cg+3
    const int rg = tid >> 5;    // rows 8*rg..8*rg+7

    unsigned long long acc01[8], acc23[8];
#pragma unroll
    for (int r = 0; r < 8; r++) { acc01[r] = 0ull; acc23[r] = 0ull; }

    const unsigned long long* xb =
        (const unsigned long long*)(Xs2 + rg * 8 * 128);
    const float* wcol = Ws + 4 * cg;

#pragma unroll 4
    for (int k = 0; k < 128; k++) {
        unsigned long long w01 =
            *(const unsigned long long*)(wcol + k * 128);
        unsigned long long w23 =
            *(const unsigned long long*)(wcol + k * 128 + 2);
#pragma unroll
        for (int r = 0; r < 8; r++) {
            unsigned long long xv = xb[r * 128 + k];
            asm("fma.rn.f32x2 %0, %1, %2, %3;"
                : "=l"(acc01[r]) : "l"(xv), "l"(w01), "l"(acc01[r]));
            asm("fma.rn.f32x2 %0, %1, %2, %3;"
                : "=l"(acc23[r]) : "l"(xv), "l"(w23), "l"(acc23[r]));
        }
    }

#pragma unroll
    for (int r = 0; r < 8; r++) {
        int gr = row0 + rg * 8 + r;
        if (gr < nrows) {
            float2 lo = *(float2*)&acc01[r];
            float2 hi = *(float2*)&acc23[r];
            ((float4*)Y)[(size_t)gr * 32 + cg] =
                make_float4(lo.x, lo.y, hi.x, hi.y);
        }
    }
}

// D_OUT=40: 320 threads (8 row-groups x 40 cols), 64 rows/block.
__global__ void gemm40_kernel(const float* __restrict__ X,
                              const float* __restrict__ W,
                              float* __restrict__ Y, int nrows) {
    extern __shared__ float sm[];
    float* Ws = sm;                 // 128*40
    float* Xs = sm + 128 * DO;      // 64*128
    const int tid = threadIdx.x;

    for (int i = tid; i < 128 * DO; i += 320) Ws[i] = W[i];

    const int row0 = blockIdx.x * 64;
    const float4* X4 = (const float4*)X;
    float4* Xs4 = (float4*)Xs;
    for (int i = tid; i < 64 * 32; i += 320) {
        int gr = row0 + (i >> 5);
        Xs4[i] = (gr < nrows) ? X4[(size_t)gr * 32 + (i & 31)]
                              : make_float4(0.f, 0.f, 0.f, 0.f);
    }
    __syncthreads();

    const int c  = tid % DO;
    const int rg = tid / DO;    // 0..7
    float acc[8];
#pragma unroll
    for (int r = 0; r < 8; r++) acc[r] = 0.f;
    const float4* xb4 = (const float4*)(Xs + rg * 8 * 128);

#pragma unroll 4
    for (int k4 = 0; k4 < 32; k4++) {
        float w0 = Ws[(4 * k4 + 0) * DO + c];
        float w1 = Ws[(4 * k4 + 1) * DO + c];
        float w2 = Ws[(4 * k4 + 2) * DO + c];
        float w3 = Ws[(4 * k4 + 3) * DO + c];
#pragma unroll
        for (int r = 0; r < 8; r++) {
            float4 xv = xb4[r * 32 + k4];
            acc[r] += xv.x * w0 + xv.y * w1 + xv.z * w2 + xv.w * w3;
        }
    }
#pragma unroll
    for (int r = 0; r < 8; r++) {
        int gr = row0 + rg * 8 + r;
        if (gr < nrows) Y[(size_t)gr * DO + c] = acc[r];
    }
}

// ----------------------- CSR gather aggregation ----------------------------
__global__ void agg128_kernel(const int* __restrict__ rowptr,
                              const int* __restrict__ esrc,
                              const float* __restrict__ ews,
                              const float* __restrict__ H,
                              const float* __restrict__ bias,
                              float* __restrict__ Y, int n) {
    int node = blockIdx.x * 8 + (threadIdx.x >> 5);
    if (node >= n) return;
    const int lane = threadIdx.x & 31;
    int beg = rowptr[node];
    int end = rowptr[node + 1];

    float4 acc = make_float4(0.f, 0.f, 0.f, 0.f);
    int j = beg;
    for (; j + 3 < end; j += 4) {
        int s0 = esrc[j];     float w0 = ews[j];
        int s1 = esrc[j + 1]; float w1 = ews[j + 1];
        int s2 = esrc[j + 2]; float w2 = ews[j + 2];
        int s3 = esrc[j + 3]; float w3 = ews[j + 3];
        float4 v0 = ((const float4*)(H + (size_t)s0 * 128))[lane];
        float4 v1 = ((const float4*)(H + (size_t)s1 * 128))[lane];
        float4 v2 = ((const float4*)(H + (size_t)s2 * 128))[lane];
        float4 v3 = ((const float4*)(H + (size_t)s3 * 128))[lane];
        acc.x += v0.x * w0 + v1.x * w1 + v2.x * w2 + v3.x * w3;
        acc.y += v0.y * w0 + v1.y * w1 + v2.y * w2 + v3.y * w3;
        acc.z += v0.z * w0 + v1.z * w1 + v2.z * w2 + v3.z * w3;
        acc.w += v0.w * w0 + v1.w * w1 + v2.w * w2 + v3.w * w3;
    }
    for (; j < end; j++) {
        int s = esrc[j]; float w = ews[j];
        float4 v = ((const float4*)(H + (size_t)s * 128))[lane];
        acc.x += v.x * w; acc.y += v.y * w; acc.z += v.z * w; acc.w += v.w * w;
    }

    float4 b = ((const float4*)bias)[lane];
    acc.x = fmaxf(acc.x + b.x, 0.f);
    acc.y = fmaxf(acc.y + b.y, 0.f);
    acc.z = fmaxf(acc.z + b.z, 0.f);
    acc.w = fmaxf(acc.w + b.w, 0.f);
    ((float4*)(Y + (size_t)node * 128))[lane] = acc;
}

// D=40 gather + bias + log_softmax, one warp per node.
__global__ void agg40_lsm_kernel(const int* __restrict__ rowptr,
                                 const int* __restrict__ esrc,
                                 const float* __restrict__ ews,
                                 const float* __restrict__ H,
                                 const float* __restrict__ b,
                                 float* __restrict__ out, int n) {
    int node = blockIdx.x * 8 + (threadIdx.x >> 5);
    if (node >= n) return;
    const int lane = threadIdx.x & 31;
    int beg = rowptr[node];
    int end = rowptr[node + 1];

    float a0 = 0.f, a1 = 0.f;
    int j = beg;
    for (; j + 1 < end; j += 2) {
        int s0 = esrc[j];     float w0 = ews[j];
        int s1 = esrc[j + 1]; float w1 = ews[j + 1];
        const float* h0 = H + (size_t)s0 * DO;
        const float* h1 = H + (size_t)s1 * DO;
        a0 += h0[lane] * w0 + h1[lane] * w1;
        if (lane < 8) a1 += h0[32 + lane] * w0 + h1[32 + lane] * w1;
    }
    if (j < end) {
        int s = esrc[j]; float w = ews[j];
        const float* hs = H + (size_t)s * DO;
        a0 += hs[lane] * w;
        if (lane < 8) a1 += hs[32 + lane] * w;
    }

    float v0 = a0 + b[lane];
    float v1 = (lane < 8) ? (a1 + b[32 + lane]) : -1e30f;

    float m = fmaxf(v0, v1);
#pragma unroll
    for (int o = 16; o; o >>= 1) m = fmaxf(m, __shfl_xor_sync(0xffffffffu, m, o));

    float sum = __expf(v0 - m) + ((lane < 8) ? __expf(v1 - m) : 0.f);
#pragma unroll
    for (int o = 16; o; o >>= 1) sum += __shfl_xor_sync(0xffffffffu, sum, o);

    float lse = m + __logf(sum);
    out[(size_t)node * DO + lane] = v0 - lse;
    if (lane < 8) out[(size_t)node * DO + 32 + lane] = v1 - lse;
}

// ---------------------------------------------------------------------------
extern "C" void kernel_launch(void* const* d_in, const int* in_sizes, int n_in,
                              void* d_out, int out_size) {
    const float* x  = (const float*)d_in[0];
    const void*  ei = d_in[1];
    const float* ew = (const float*)d_in[2];
    const float* W1 = (const float*)d_in[3];
    const float* b1 = (const float*)d_in[4];
    const float* W2 = (const float*)d_in[5];
    const float* b2 = (const float*)d_in[6];
    const float* W3 = (const float*)d_in[7];
    const float* b3 = (const float*)d_in[8];
    float* out = (float*)d_out;

    const int n  = in_sizes[0] / DH;
    int ne = in_sizes[1] / 2;
    if (ne > MAXE) ne = MAXE;
    (void)n_in; (void)out_size;

    float *A, *B;
    int *rowptr, *deg, *fill, *esrc, *partials;
    float* ews;
    cudaGetSymbolAddress((void**)&A, g_bufA);
    cudaGetSymbolAddress((void**)&B, g_bufB);
    cudaGetSymbolAddress((void**)&rowptr, g_rowptr);
    cudaGetSymbolAddress((void**)&deg, g_deg);
    cudaGetSymbolAddress((void**)&fill, g_fill);
    cudaGetSymbolAddress((void**)&esrc, g_esrc);
    cudaGetSymbolAddress((void**)&ews, g_ews);
    cudaGetSymbolAddress((void**)&partials, g_partials);

    // W (64 KB) + duplicated X tile (64 rows * 128 * 8 B = 64 KB) = 128 KB
    const int SMEM128 = (128 * 128) * (int)sizeof(float)
                      + (64 * 128) * (int)sizeof(float2);
    const int SMEM40  = (128 * DO + 64 * 128) * (int)sizeof(float);
    cudaFuncSetAttribute(gemm128_kernel,
                         cudaFuncAttributeMaxDynamicSharedMemorySize, SMEM128);
    cudaFuncSetAttribute(gemm40_kernel,
                         cudaFuncAttributeMaxDynamicSharedMemorySize, SMEM40);

    const int gemmBlocks     = (n + 63) / 64;
    const int nodeWarpBlocks = (n + 7) / 8;
    const int scanBlocks     = (n + 1023) / 1024;

    static cudaStream_t s2 = nullptr;
    static cudaEvent_t evFork = nullptr, evJoin = nullptr;
    if (s2 == nullptr) {
        cudaStreamCreateWithFlags(&s2, cudaStreamNonBlocking);
        cudaEventCreateWithFlags(&evFork, cudaEventDisableTiming);
        cudaEventCreateWithFlags(&evJoin, cudaEventDisableTiming);
    }

    // ---- fork: CSR build (by dst) on side stream ----
    cudaEventRecord(evFork, 0);
    cudaStreamWaitEvent(s2, evFork, 0);
    deg_zero_kernel<<<(n + 255) / 256, 256, 0, s2>>>(deg, n, ei, n);
    deg_count_kernel<<<(ne + 255) / 256, 256, 0, s2>>>(ei, ne, deg);
    scan_block_kernel<<<scanBlocks, 1024, 0, s2>>>(deg, rowptr, partials, n);
    scan_partials_kernel<<<1, 128, 0, s2>>>(partials, scanBlocks);
    scan_add_kernel<<<(n + 255) / 256, 256, 0, s2>>>(rowptr, partials, fill, n, ne);
    csr_fill_kernel<<<(ne + 255) / 256, 256, 0, s2>>>(ei, ew, ne, fill, esrc, ews);
    cudaEventRecord(evJoin, s2);

    // ---- main stream: layer-1 GEMM overlaps CSR build ----
    gemm128_kernel<<<gemmBlocks, 256, SMEM128>>>(x, W1, A, n);

    // ---- join ----
    cudaStreamWaitEvent(0, evJoin, 0);

    // ---- layer 1 aggregation ----
    agg128_kernel<<<nodeWarpBlocks, 256>>>(rowptr, esrc, ews, A, b1, B, n);
    // ---- layer 2 ----
    gemm128_kernel<<<gemmBlocks, 256, SMEM128>>>(B, W2, A, n);
    agg128_kernel<<<nodeWarpBlocks, 256>>>(rowptr, esrc, ews, A, b2, B, n);
    // ---- layer 3 (D_OUT = 40) ----
    gemm40_kernel<<<gemmBlocks, 320, SMEM40>>>(B, W3, A, n);
    agg40_lsm_kernel<<<nodeWarpBlocks, 256>>>(rowptr, esrc, ews, A, b3, out, n);
}

// round 8
// speedup vs baseline: 1.3087x; 1.3087x over previous
#include <cuda_runtime.h>
#include <cuda_bf16.h>
#include <mma.h>
#include <cstdint>

using namespace nvcuda;

// ---------------------------------------------------------------------------
// AdjGCN: 3-layer GCN forward.
//  - CSR-gather aggregation (no float atomics), CSR built on a forked stream.
//  - 128x128 GEMMs on wmma (HMMA tensor path, baseline PTX), bf16x3 split:
//      X@W ~= Xhi@Whi + Xhi@Wlo + Xlo@Whi   (f32 accumulators)
// ---------------------------------------------------------------------------

#define MAXN 100000
#define MAXNP 100096   // padded to multiple of 64 (wmma tail-block stores)
#define MAXE 1600000
#define DH   128
#define DO   40
#define LDX  136       // smem leading dims (bank-conflict-free ldmatrix)
#define LDW  136

__device__ float         g_bufA[(size_t)MAXNP * DH];
__device__ float         g_bufB[(size_t)MAXNP * DH];
__device__ int           g_idx64;
__device__ int           g_rowptr[MAXN + 1];
__device__ int           g_deg[MAXN];
__device__ int           g_fill[MAXN];
__device__ int           g_esrc[MAXE];
__device__ float         g_ews[MAXE];
__device__ int           g_partials[128];
__device__ __nv_bfloat16 g_w1hi[128 * 128];
__device__ __nv_bfloat16 g_w1lo[128 * 128];
__device__ __nv_bfloat16 g_w2hi[128 * 128];
__device__ __nv_bfloat16 g_w2lo[128 * 128];

// ---------------------------------------------------------------------------
__device__ __forceinline__ void load_edge(const void* ei, int nedges, int e,
                                          int& s, int& d) {
    if (g_idx64) {
        const long long* p = (const long long*)ei;
        s = (int)p[e];
        d = (int)p[(size_t)nedges + e];
    } else {
        const int* p = (const int*)ei;
        s = p[e];
        d = p[(size_t)nedges + e];
    }
}

// ------------------------------ CSR build ---------------------------------
__global__ void deg_zero_kernel(int* __restrict__ deg, int n,
                                const void* ei, int n_nodes) {
    int i = blockIdx.x * blockDim.x + threadIdx.x;
    if (i < n) deg[i] = 0;
    if (blockIdx.x == 0 && threadIdx.x == 0) {
        const long long* p = (const long long*)ei;
        int ok64 = 1;
        for (int k = 0; k < 32; k++) {
            long long v = p[k];
            if (v < 0 || v >= n_nodes) { ok64 = 0; break; }
        }
        g_idx64 = ok64;
    }
}

__global__ void deg_count_kernel(const void* __restrict__ ei, int ne,
                                 int* __restrict__ deg) {
    int e = blockIdx.x * blockDim.x + threadIdx.x;
    if (e < ne) {
        int s, d;
        load_edge(ei, ne, e, s, d);
        atomicAdd(&deg[d], 1);
    }
}

__global__ void scan_block_kernel(const int* __restrict__ deg,
                                  int* __restrict__ rowptr,
                                  int* __restrict__ partials, int n) {
    __shared__ int sm[1024];
    const int tid = threadIdx.x;
    int i = blockIdx.x * 1024 + tid;
    int v = (i < n) ? deg[i] : 0;
    sm[tid] = v;
    __syncthreads();
#pragma unroll
    for (int o = 1; o < 1024; o <<= 1) {
        int t = (tid >= o) ? sm[tid - o] : 0;
        __syncthreads();
        sm[tid] += t;
        __syncthreads();
    }
    if (i < n) rowptr[i] = sm[tid] - v;
    if (tid == 1023) partials[blockIdx.x] = sm[1023];
}

__global__ void scan_partials_kernel(int* __restrict__ partials, int nb) {
    __shared__ int sm[128];
    const int tid = threadIdx.x;
    int v = (tid < nb) ? partials[tid] : 0;
    sm[tid] = v;
    __syncthreads();
#pragma unroll
    for (int o = 1; o < 128; o <<= 1) {
        int t = (tid >= o) ? sm[tid - o] : 0;
        __syncthreads();
        sm[tid] += t;
        __syncthreads();
    }
    if (tid < nb) partials[tid] = sm[tid] - v;
}

__global__ void scan_add_kernel(int* __restrict__ rowptr,
                                const int* __restrict__ partials,
                                int* __restrict__ fill, int n, int ne) {
    int i = blockIdx.x * blockDim.x + threadIdx.x;
    if (i < n) {
        int v = rowptr[i] + partials[i >> 10];
        rowptr[i] = v;
        fill[i] = v;
    }
    if (i == 0) rowptr[n] = ne;
}

__global__ void csr_fill_kernel(const void* __restrict__ ei,
                                const float* __restrict__ ew, int ne,
                                int* __restrict__ fill,
                                int* __restrict__ esrc,
                                float* __restrict__ ews) {
    int e = blockIdx.x * blockDim.x + threadIdx.x;
    if (e < ne) {
        int s, d;
        load_edge(ei, ne, e, s, d);
        int pos = atomicAdd(&fill[d], 1);
        esrc[pos] = s;
        ews[pos] = ew[e];
    }
}

// ------------------- W prep: fp32 -> bf16 hi/lo (row-major) ----------------
__global__ void prep_w_kernel(const float* __restrict__ W,
                              __nv_bfloat16* __restrict__ hi,
                              __nv_bfloat16* __restrict__ lo) {
    int i = blockIdx.x * blockDim.x + threadIdx.x;
    if (i < 128 * 128) {
        float w = W[i];
        __nv_bfloat16 h = __float2bfloat16_rn(w);
        hi[i] = h;
        lo[i] = __float2bfloat16_rn(w - __bfloat162float(h));
    }
}

// -------------------- tensor-path GEMM (wmma bf16x3) -----------------------
// Block: 256 threads (8 warps), 64 rows x 128 cols. Warp (wr,wc) in 2x4 grid
// owns a 32x32 tile = 2x2 wmma 16x16 fragments. K=128 in 8 steps of 16.
__global__ void gemm128_tc_kernel(const float* __restrict__ X,
                                  const __nv_bfloat16* __restrict__ Whi,
                                  const __nv_bfloat16* __restrict__ Wlo,
                                  float* __restrict__ Y, int nrows) {
    extern __shared__ char smem[];
    __nv_bfloat16* xhi = (__nv_bfloat16*)smem;        // 64 * LDX
    __nv_bfloat16* xlo = xhi + 64 * LDX;              // 64 * LDX
    __nv_bfloat16* wh  = xlo + 64 * LDX;              // 128 * LDW
    __nv_bfloat16* wl  = wh + 128 * LDW;              // 128 * LDW
    const int tid = threadIdx.x;
    const int row0 = blockIdx.x * 64;

    // Stage X, splitting fp32 -> bf16 hi/lo.
    {
        const float4* X4 = (const float4*)X;
#pragma unroll
        for (int i = tid; i < 64 * 32; i += 256) {
            int r = i >> 5, kq = i & 31;
            float4 v = (row0 + r < nrows)
                           ? X4[(size_t)(row0 + r) * 32 + kq]
                           : make_float4(0.f, 0.f, 0.f, 0.f);
            __nv_bfloat16 hx = __float2bfloat16_rn(v.x);
            __nv_bfloat16 hy = __float2bfloat16_rn(v.y);
            __nv_bfloat16 hz = __float2bfloat16_rn(v.z);
            __nv_bfloat16 hw = __float2bfloat16_rn(v.w);
            __nv_bfloat162 hp0 = __halves2bfloat162(hx, hy);
            __nv_bfloat162 hp1 = __halves2bfloat162(hz, hw);
            uint64_t hword = (uint64_t)(*(uint32_t*)&hp0)
                           | ((uint64_t)(*(uint32_t*)&hp1) << 32);
            *(uint64_t*)&xhi[r * LDX + kq * 4] = hword;
            __nv_bfloat162 lp0 = __halves2bfloat162(
                __float2bfloat16_rn(v.x - __bfloat162float(hx)),
                __float2bfloat16_rn(v.y - __bfloat162float(hy)));
            __nv_bfloat162 lp1 = __halves2bfloat162(
                __float2bfloat16_rn(v.z - __bfloat162float(hz)),
                __float2bfloat16_rn(v.w - __bfloat162float(hw)));
            uint64_t lword = (uint64_t)(*(uint32_t*)&lp0)
                           | ((uint64_t)(*(uint32_t*)&lp1) << 32);
            *(uint64_t*)&xlo[r * LDX + kq * 4] = lword;
        }
    }
    // Copy W hi/lo blobs into padded smem rows (int4 chunks of 8 bf16).
    {
        const int4* h4 = (const int4*)Whi;
        const int4* l4 = (const int4*)Wlo;
#pragma unroll
        for (int i = tid; i < 2048; i += 256) {
            int k = i >> 4, seg = i & 15;
            *(int4*)&wh[k * LDW + seg * 8] = h4[i];
            *(int4*)&wl[k * LDW + seg * 8] = l4[i];
        }
    }
    __syncthreads();

    const int w  = tid >> 5;
    const int wr = w >> 2;     // 0..1
    const int wc = w & 3;      // 0..3

    wmma::fragment<wmma::accumulator, 16, 16, 16, float> acc[2][2];
#pragma unroll
    for (int i = 0; i < 2; i++)
#pragma unroll
        for (int j = 0; j < 2; j++) wmma::fill_fragment(acc[i][j], 0.f);

#pragma unroll
    for (int ks = 0; ks < 8; ks++) {
        const int k0 = ks * 16;
        wmma::fragment<wmma::matrix_a, 16, 16, 16, __nv_bfloat16,
                       wmma::row_major> ah[2], al[2];
        wmma::fragment<wmma::matrix_b, 16, 16, 16, __nv_bfloat16,
                       wmma::row_major> bh[2], bl[2];
#pragma unroll
        for (int i = 0; i < 2; i++) {
            wmma::load_matrix_sync(ah[i], &xhi[(wr * 32 + i * 16) * LDX + k0], LDX);
            wmma::load_matrix_sync(al[i], &xlo[(wr * 32 + i * 16) * LDX + k0], LDX);
        }
#pragma unroll
        for (int j = 0; j < 2; j++) {
            wmma::load_matrix_sync(bh[j], &wh[k0 * LDW + wc * 32 + j * 16], LDW);
            wmma::load_matrix_sync(bl[j], &wl[k0 * LDW + wc * 32 + j * 16], LDW);
        }
#pragma unroll
        for (int i = 0; i < 2; i++)
#pragma unroll
            for (int j = 0; j < 2; j++) {
                wmma::mma_sync(acc[i][j], ah[i], bh[j], acc[i][j]);
                wmma::mma_sync(acc[i][j], ah[i], bl[j], acc[i][j]);
                wmma::mma_sync(acc[i][j], al[i], bh[j], acc[i][j]);
            }
    }

    // Store. Y is padded to MAXNP rows, so tail-block stores stay in-bounds.
#pragma unroll
    for (int i = 0; i < 2; i++)
#pragma unroll
        for (int j = 0; j < 2; j++) {
            int gr = row0 + wr * 32 + i * 16;
            int gc = wc * 32 + j * 16;
            wmma::store_matrix_sync(&Y[(size_t)gr * 128 + gc], acc[i][j],
                                    128, wmma::mem_row_major);
        }
}

// ------------------------- SIMT GEMM, D_OUT=40 ------------------------------
__global__ void gemm40_kernel(const float* __restrict__ X,
                              const float* __restrict__ W,
                              float* __restrict__ Y, int nrows) {
    extern __shared__ float sm[];
    float* Ws = sm;
    float* Xs = sm + 128 * DO;
    const int tid = threadIdx.x;

    for (int i = tid; i < 128 * DO; i += 320) Ws[i] = W[i];

    const int row0 = blockIdx.x * 64;
    const float4* X4 = (const float4*)X;
    float4* Xs4 = (float4*)Xs;
    for (int i = tid; i < 64 * 32; i += 320) {
        int gr = row0 + (i >> 5);
        Xs4[i] = (gr < nrows) ? X4[(size_t)gr * 32 + (i & 31)]
                              : make_float4(0.f, 0.f, 0.f, 0.f);
    }
    __syncthreads();

    const int c  = tid % DO;
    const int rg = tid / DO;
    float acc[8];
#pragma unroll
    for (int r = 0; r < 8; r++) acc[r] = 0.f;
    const float4* xb4 = (const float4*)(Xs + rg * 8 * 128);

#pragma unroll 4
    for (int k4 = 0; k4 < 32; k4++) {
        float w0 = Ws[(4 * k4 + 0) * DO + c];
        float w1 = Ws[(4 * k4 + 1) * DO + c];
        float w2 = Ws[(4 * k4 + 2) * DO + c];
        float w3 = Ws[(4 * k4 + 3) * DO + c];
#pragma unroll
        for (int r = 0; r < 8; r++) {
            float4 xv = xb4[r * 32 + k4];
            acc[r] += xv.x * w0 + xv.y * w1 + xv.z * w2 + xv.w * w3;
        }
    }
#pragma unroll
    for (int r = 0; r < 8; r++) {
        int gr = row0 + rg * 8 + r;
        if (gr < nrows) Y[(size_t)gr * DO + c] = acc[r];
    }
}

// ----------------------- CSR gather aggregation ----------------------------
__global__ void agg128_kernel(const int* __restrict__ rowptr,
                              const int* __restrict__ esrc,
                              const float* __restrict__ ews,
                              const float* __restrict__ H,
                              const float* __restrict__ bias,
                              float* __restrict__ Y, int n) {
    int node = blockIdx.x * 8 + (threadIdx.x >> 5);
    if (node >= n) return;
    const int lane = threadIdx.x & 31;
    int beg = rowptr[node];
    int end = rowptr[node + 1];

    float4 acc = make_float4(0.f, 0.f, 0.f, 0.f);
    int j = beg;
    for (; j + 3 < end; j += 4) {
        int s0 = esrc[j];     float w0 = ews[j];
        int s1 = esrc[j + 1]; float w1 = ews[j + 1];
        int s2 = esrc[j + 2]; float w2 = ews[j + 2];
        int s3 = esrc[j + 3]; float w3 = ews[j + 3];
        float4 v0 = ((const float4*)(H + (size_t)s0 * 128))[lane];
        float4 v1 = ((const float4*)(H + (size_t)s1 * 128))[lane];
        float4 v2 = ((const float4*)(H + (size_t)s2 * 128))[lane];
        float4 v3 = ((const float4*)(H + (size_t)s3 * 128))[lane];
        acc.x += v0.x * w0 + v1.x * w1 + v2.x * w2 + v3.x * w3;
        acc.y += v0.y * w0 + v1.y * w1 + v2.y * w2 + v3.y * w3;
        acc.z += v0.z * w0 + v1.z * w1 + v2.z * w2 + v3.z * w3;
        acc.w += v0.w * w0 + v1.w * w1 + v2.w * w2 + v3.w * w3;
    }
    for (; j < end; j++) {
        int s = esrc[j]; float w = ews[j];
        float4 v = ((const float4*)(H + (size_t)s * 128))[lane];
        acc.x += v.x * w; acc.y += v.y * w; acc.z += v.z * w; acc.w += v.w * w;
    }

    float4 b = ((const float4*)bias)[lane];
    acc.x = fmaxf(acc.x + b.x, 0.f);
    acc.y = fmaxf(acc.y + b.y, 0.f);
    acc.z = fmaxf(acc.z + b.z, 0.f);
    acc.w = fmaxf(acc.w + b.w, 0.f);
    ((float4*)(Y + (size_t)node * 128))[lane] = acc;
}

__global__ void agg40_lsm_kernel(const int* __restrict__ rowptr,
                                 const int* __restrict__ esrc,
                                 const float* __restrict__ ews,
                                 const float* __restrict__ H,
                                 const float* __restrict__ b,
                                 float* __restrict__ out, int n) {
    int node = blockIdx.x * 8 + (threadIdx.x >> 5);
    if (node >= n) return;
    const int lane = threadIdx.x & 31;
    int beg = rowptr[node];
    int end = rowptr[node + 1];

    float a0 = 0.f, a1 = 0.f;
    int j = beg;
    for (; j + 1 < end; j += 2) {
        int s0 = esrc[j];     float w0 = ews[j];
        int s1 = esrc[j + 1]; float w1 = ews[j + 1];
        const float* h0 = H + (size_t)s0 * DO;
        const float* h1 = H + (size_t)s1 * DO;
        a0 += h0[lane] * w0 + h1[lane] * w1;
        if (lane < 8) a1 += h0[32 + lane] * w0 + h1[32 + lane] * w1;
    }
    if (j < end) {
        int s = esrc[j]; float w = ews[j];
        const float* hs = H + (size_t)s * DO;
        a0 += hs[lane] * w;
        if (lane < 8) a1 += hs[32 + lane] * w;
    }

    float v0 = a0 + b[lane];
    float v1 = (lane < 8) ? (a1 + b[32 + lane]) : -1e30f;

    float m = fmaxf(v0, v1);
#pragma unroll
    for (int o = 16; o; o >>= 1) m = fmaxf(m, __shfl_xor_sync(0xffffffffu, m, o));

    float sum = __expf(v0 - m) + ((lane < 8) ? __expf(v1 - m) : 0.f);
#pragma unroll
    for (int o = 16; o; o >>= 1) sum += __shfl_xor_sync(0xffffffffu, sum, o);

    float lse = m + __logf(sum);
    out[(size_t)node * DO + lane] = v0 - lse;
    if (lane < 8) out[(size_t)node * DO + 32 + lane] = v1 - lse;
}

// ---------------------------------------------------------------------------
extern "C" void kernel_launch(void* const* d_in, const int* in_sizes, int n_in,
                              void* d_out, int out_size) {
    const float* x  = (const float*)d_in[0];
    const void*  ei = d_in[1];
    const float* ew = (const float*)d_in[2];
    const float* W1 = (const float*)d_in[3];
    const float* b1 = (const float*)d_in[4];
    const float* W2 = (const float*)d_in[5];
    const float* b2 = (const float*)d_in[6];
    const float* W3 = (const float*)d_in[7];
    const float* b3 = (const float*)d_in[8];
    float* out = (float*)d_out;

    const int n  = in_sizes[0] / DH;
    int ne = in_sizes[1] / 2;
    if (ne > MAXE) ne = MAXE;
    (void)n_in; (void)out_size;

    float *A, *B;
    int *rowptr, *deg, *fill, *esrc, *partials;
    float* ews;
    __nv_bfloat16 *w1hi, *w1lo, *w2hi, *w2lo;
    cudaGetSymbolAddress((void**)&A, g_bufA);
    cudaGetSymbolAddress((void**)&B, g_bufB);
    cudaGetSymbolAddress((void**)&rowptr, g_rowptr);
    cudaGetSymbolAddress((void**)&deg, g_deg);
    cudaGetSymbolAddress((void**)&fill, g_fill);
    cudaGetSymbolAddress((void**)&esrc, g_esrc);
    cudaGetSymbolAddress((void**)&ews, g_ews);
    cudaGetSymbolAddress((void**)&partials, g_partials);
    cudaGetSymbolAddress((void**)&w1hi, g_w1hi);
    cudaGetSymbolAddress((void**)&w1lo, g_w1lo);
    cudaGetSymbolAddress((void**)&w2hi, g_w2hi);
    cudaGetSymbolAddress((void**)&w2lo, g_w2lo);

    // smem: xhi+xlo (2*64*136*2B) + whi+wlo (2*128*136*2B) = 104448 B
    const int SMEM_TC = (2 * 64 * LDX + 2 * 128 * LDW) * (int)sizeof(__nv_bfloat16);
    const int SMEM40  = (128 * DO + 64 * 128) * (int)sizeof(float);
    cudaFuncSetAttribute(gemm128_tc_kernel,
                         cudaFuncAttributeMaxDynamicSharedMemorySize, SMEM_TC);
    cudaFuncSetAttribute(gemm40_kernel,
                         cudaFuncAttributeMaxDynamicSharedMemorySize, SMEM40);

    const int tcBlocks       = (n + 63) / 64;
    const int nodeWarpBlocks = (n + 7) / 8;
    const int scanBlocks     = (n + 1023) / 1024;

    static cudaStream_t s2 = nullptr;
    static cudaEvent_t evFork = nullptr, evJoin = nullptr;
    if (s2 == nullptr) {
        cudaStreamCreateWithFlags(&s2, cudaStreamNonBlocking);
        cudaEventCreateWithFlags(&evFork, cudaEventDisableTiming);
        cudaEventCreateWithFlags(&evJoin, cudaEventDisableTiming);
    }

    // ---- fork: CSR build on side stream ----
    cudaEventRecord(evFork, 0);
    cudaStreamWaitEvent(s2, evFork, 0);
    deg_zero_kernel<<<(n + 255) / 256, 256, 0, s2>>>(deg, n, ei, n);
    deg_count_kernel<<<(ne + 255) / 256, 256, 0, s2>>>(ei, ne, deg);
    scan_block_kernel<<<scanBlocks, 1024, 0, s2>>>(deg, rowptr, partials, n);
    scan_partials_kernel<<<1, 128, 0, s2>>>(partials, scanBlocks);
    scan_add_kernel<<<(n + 255) / 256, 256, 0, s2>>>(rowptr, partials, fill, n, ne);
    csr_fill_kernel<<<(ne + 255) / 256, 256, 0, s2>>>(ei, ew, ne, fill, esrc, ews);
    cudaEventRecord(evJoin, s2);

    // ---- main stream: W prep + layer-1 GEMM overlap the CSR build ----
    prep_w_kernel<<<64, 256>>>(W1, w1hi, w1lo);
    prep_w_kernel<<<64, 256>>>(W2, w2hi, w2lo);
    gemm128_tc_kernel<<<tcBlocks, 256, SMEM_TC>>>(x, w1hi, w1lo, A, n);

    // ---- join ----
    cudaStreamWaitEvent(0, evJoin, 0);

    // ---- layer 1 aggregation ----
    agg128_kernel<<<nodeWarpBlocks, 256>>>(rowptr, esrc, ews, A, b1, B, n);
    // ---- layer 2 ----
    gemm128_tc_kernel<<<tcBlocks, 256, SMEM_TC>>>(B, w2hi, w2lo, A, n);
    agg128_kernel<<<nodeWarpBlocks, 256>>>(rowptr, esrc, ews, A, b2, B, n);
    // ---- layer 3 (D_OUT = 40) ----
    gemm40_kernel<<<tcBlocks, 320, SMEM40>>>(B, W3, A, n);
    agg40_lsm_kernel<<<nodeWarpBlocks, 256>>>(rowptr, esrc, ews, A, b3, out, n);
}